// round 5
// baseline (speedup 1.0000x reference)
#include <cuda_runtime.h>
#include <math.h>

// Problem constants
constexpr int B   = 8;
constexpr int R   = 128;
constexpr int H   = 256;
constexpr int IND = 512;
constexpr int L   = 3;
constexpr int NH  = 4;
constexpr int DH  = 64;

constexpr int SZ = B * R * H;  // 262144
constexpr int HH = H * H;
constexpr int NCTA = 256;

// Scratch layout
constexpr int OFF_H    = 0;
constexpr int OFF_AACT = SZ;
constexpr int OFF_BB   = 2 * SZ;
constexpr int OFF_AGG  = 3 * SZ;
constexpr int OFF_HU   = 4 * SZ;
constexpr int OFF_UPRE = 5 * SZ;
constexpr int OFF_U    = 6 * SZ;
constexpr int OFF_Q    = 7 * SZ;
constexpr int OFF_K    = 8 * SZ;
constexpr int OFF_V    = 9 * SZ;
constexpr int OFF_AO   = 10 * SZ;
constexpr int OFF_ADJ  = 11 * SZ;                 // R*R
constexpr int OFF_RS   = OFF_ADJ + R * R;         // R
constexpr int OFF_W2U  = OFF_RS + R;              // L*H*H
constexpr int OFF_C2   = OFF_W2U + L * HH;        // L*H
constexpr int TOTAL    = OFF_C2 + L * H;

__device__ float g_buf[TOTAL];
__device__ unsigned g_barcnt = 0;
__device__ volatile unsigned g_bargen = 0;

typedef unsigned long long u64;

__device__ __forceinline__ u64 pack2(float x) {
    u64 r; asm("mov.b64 %0, {%1, %1};" : "=l"(r) : "f"(x)); return r;
}
__device__ __forceinline__ void fma2(u64& d, u64 a, u64 b) {
    asm("fma.rn.f32x2 %0, %1, %2, %0;" : "+l"(d) : "l"(a), "l"(b));
}
__device__ __forceinline__ float2 unpack2(u64 v) {
    float2 f; asm("mov.b64 {%0, %1}, %2;" : "=f"(f.x), "=f"(f.y) : "l"(v)); return f;
}

// Grid-wide barrier: all NCTA CTAs are co-resident by construction.
__device__ __forceinline__ void gsync(unsigned target) {
    __syncthreads();
    if (threadIdx.x == 0) {
        __threadfence();
        unsigned old = atomicAdd(&g_barcnt, 1u);
        if (old == NCTA - 1) {
            g_barcnt = 0;
            __threadfence();
            g_bargen = target;
        } else {
            while (g_bargen != target) { }
        }
        __threadfence();
    }
    __syncthreads();
}

// ---------------------------------------------------------------------------
// One 64x64 output tile of C = act(A@W [+addend] [+bias] [+rowv[m&127]*colv]).
// K = N_stride = 256. 256 threads, BK=16 double-buffered, f32x2 accumulation.
__device__ __forceinline__ void gemm_tile(
    const float* __restrict__ A, const float* __restrict__ W,
    const float* bias, const float* rowv, const float* colv,
    const float* addend, float* C, int relu, int m0, int n0, float* sh)
{
    const int t = threadIdx.x;
    float* As = sh;            // [2][16][68]  (As[buf][k][m])
    float* Ws = sh + 2176;     // [2][16][64]
    const int ar = t >> 2, ac = (t & 3) * 4;     // A gmem load: row, k4
    const int wr = t >> 4, wc = (t & 15) * 4;    // W gmem load: k, n4
    const int mg = (t >> 3) * 2;                 // 0..62
    const int ng = (t & 7) * 8;                  // 0..56

    u64 acc[8];
    #pragma unroll
    for (int i = 0; i < 8; i++) acc[i] = 0ull;

    const float* Aptr = A + (m0 + ar) * 256 + ac;
    const float* Wptr = W + wr * 256 + n0 + wc;

    float4 aR = *(const float4*)Aptr;
    float4 wR = *(const float4*)Wptr;
    {
        float* a0 = As;
        a0[(ac + 0) * 68 + ar] = aR.x; a0[(ac + 1) * 68 + ar] = aR.y;
        a0[(ac + 2) * 68 + ar] = aR.z; a0[(ac + 3) * 68 + ar] = aR.w;
        *(float4*)(Ws + wr * 64 + wc) = wR;
    }
    __syncthreads();

    #pragma unroll 1
    for (int kt = 0; kt < 16; kt++) {
        const int cur = kt & 1;
        if (kt < 15) {
            aR = *(const float4*)(Aptr + (kt + 1) * 16);
            wR = *(const float4*)(Wptr + (kt + 1) * 16 * 256);
        }
        const float* as = As + cur * 1088;
        const float* ws = Ws + cur * 1024;
        #pragma unroll
        for (int kk = 0; kk < 16; kk++) {
            float2 av = *(const float2*)(as + kk * 68 + mg);
            ulonglong2 w0 = *(const ulonglong2*)(ws + kk * 64 + ng);
            ulonglong2 w1 = *(const ulonglong2*)(ws + kk * 64 + ng + 4);
            u64 p0 = pack2(av.x), p1 = pack2(av.y);
            fma2(acc[0], p0, w0.x); fma2(acc[1], p0, w0.y);
            fma2(acc[2], p0, w1.x); fma2(acc[3], p0, w1.y);
            fma2(acc[4], p1, w0.x); fma2(acc[5], p1, w0.y);
            fma2(acc[6], p1, w1.x); fma2(acc[7], p1, w1.y);
        }
        if (kt < 15) {
            float* a1 = As + (cur ^ 1) * 1088;
            a1[(ac + 0) * 68 + ar] = aR.x; a1[(ac + 1) * 68 + ar] = aR.y;
            a1[(ac + 2) * 68 + ar] = aR.z; a1[(ac + 3) * 68 + ar] = aR.w;
            *(float4*)(Ws + (cur ^ 1) * 1024 + wr * 64 + wc) = wR;
        }
        __syncthreads();
    }

    float4 bi0, bi1, cv0, cv1;
    if (bias) {
        bi0 = *(const float4*)&bias[n0 + ng];
        bi1 = *(const float4*)&bias[n0 + ng + 4];
    }
    if (rowv) {
        cv0 = *(const float4*)&colv[n0 + ng];
        cv1 = *(const float4*)&colv[n0 + ng + 4];
    }
    #pragma unroll
    for (int i = 0; i < 2; i++) {
        const int m = m0 + mg + i;
        float2 q0 = unpack2(acc[i * 4 + 0]);
        float2 q1 = unpack2(acc[i * 4 + 1]);
        float2 q2 = unpack2(acc[i * 4 + 2]);
        float2 q3 = unpack2(acc[i * 4 + 3]);
        float4 v0 = make_float4(q0.x, q0.y, q1.x, q1.y);
        float4 v1 = make_float4(q2.x, q2.y, q3.x, q3.y);
        if (addend) {
            float4 a0 = *(const float4*)&addend[m * 256 + n0 + ng];
            float4 a1 = *(const float4*)&addend[m * 256 + n0 + ng + 4];
            v0.x += a0.x; v0.y += a0.y; v0.z += a0.z; v0.w += a0.w;
            v1.x += a1.x; v1.y += a1.y; v1.z += a1.z; v1.w += a1.w;
        }
        if (bias) {
            v0.x += bi0.x; v0.y += bi0.y; v0.z += bi0.z; v0.w += bi0.w;
            v1.x += bi1.x; v1.y += bi1.y; v1.z += bi1.z; v1.w += bi1.w;
        }
        if (rowv) {
            float rv = rowv[m & (R - 1)];
            v0.x += rv * cv0.x; v0.y += rv * cv0.y; v0.z += rv * cv0.z; v0.w += rv * cv0.w;
            v1.x += rv * cv1.x; v1.y += rv * cv1.y; v1.z += rv * cv1.z; v1.w += rv * cv1.w;
        }
        if (relu) {
            v0.x = fmaxf(v0.x, 0.f); v0.y = fmaxf(v0.y, 0.f);
            v0.z = fmaxf(v0.z, 0.f); v0.w = fmaxf(v0.w, 0.f);
            v1.x = fmaxf(v1.x, 0.f); v1.y = fmaxf(v1.y, 0.f);
            v1.z = fmaxf(v1.z, 0.f); v1.w = fmaxf(v1.w, 0.f);
        }
        *(float4*)&C[m * 256 + n0 + ng] = v0;
        *(float4*)&C[m * 256 + n0 + ng + 4] = v1;
    }
}

// ---------------------------------------------------------------------------
__global__ __launch_bounds__(256, 2) void mega_kernel(
    const float* __restrict__ x, const float* __restrict__ We, const float* __restrict__ be,
    const float* __restrict__ msg_W1, const float* __restrict__ msg_b1,
    const float* __restrict__ msg_W2, const float* __restrict__ msg_b2,
    const float* __restrict__ upd_W1, const float* __restrict__ upd_b1,
    const float* __restrict__ upd_W2, const float* __restrict__ upd_b2,
    const float* __restrict__ ln_g, const float* __restrict__ ln_b,
    const float* __restrict__ rule_adj,
    const float* __restrict__ Wq, const float* __restrict__ bq,
    const float* __restrict__ Wk, const float* __restrict__ bk,
    const float* __restrict__ Wv, const float* __restrict__ bv,
    const float* __restrict__ Wo, const float* __restrict__ bo,
    const float* __restrict__ roW1, const float* __restrict__ rob1,
    const float* __restrict__ roW2, const float* __restrict__ rob2,
    float* __restrict__ out)
{
    __shared__ float sh[12288];   // 48 KB
    const int cta = blockIdx.x;
    const int t = threadIdx.x;
    const int wid = t >> 5, lane = t & 31;

    float* hb    = g_buf + OFF_H;
    float* aact  = g_buf + OFF_AACT;
    float* bbb   = g_buf + OFF_BB;
    float* aggb  = g_buf + OFF_AGG;
    float* hub   = g_buf + OFF_HU;
    float* upreb = g_buf + OFF_UPRE;
    float* ub    = g_buf + OFF_U;
    float* qb    = g_buf + OFF_Q;
    float* kb    = g_buf + OFF_K;
    float* vb    = g_buf + OFF_V;
    float* aob   = g_buf + OFF_AO;
    float* Ab    = g_buf + OFF_ADJ;
    float* rsb   = g_buf + OFF_RS;
    float* w2ub  = g_buf + OFF_W2U;
    float* c2b   = g_buf + OFF_C2;

    unsigned gen = 0;
    if (t == 0) gen = g_bargen;

    // ---------------- Phase 0: setup (all independent) ----------------
    if (cta < 48) {
        // W2u[l] = msg_W2[l] @ upd_W1b[l]
        int l = cta >> 4, rem = cta & 15;
        gemm_tile(msg_W2 + l * HH, upd_W1 + l * 2 * HH + HH,
                  nullptr, nullptr, nullptr, nullptr, w2ub + l * HH, 0,
                  (rem >> 2) * 64, (rem & 3) * 64, sh);
    } else if (cta < 64) {
        // prep_A: warp per row
        int i = (cta - 48) * 8 + wid;
        float4 va = *(const float4*)&rule_adj[i * R + lane * 4];
        float s0 = 1.f / (1.f + expf(-va.x));
        float s1 = 1.f / (1.f + expf(-va.y));
        float s2 = 1.f / (1.f + expf(-va.z));
        float s3 = 1.f / (1.f + expf(-va.w));
        int c = lane * 4;
        if (i == c + 0) s0 = 0.f;
        if (i == c + 1) s1 = 0.f;
        if (i == c + 2) s2 = 0.f;
        if (i == c + 3) s3 = 0.f;
        *(float4*)&Ab[i * R + c] = make_float4(s0, s1, s2, s3);
        float part = s0 + s1 + s2 + s3;
        for (int o = 16; o; o >>= 1) part += __shfl_xor_sync(0xffffffffu, part, o);
        if (lane == 0) rsb[i] = part;
    } else if (cta < 72) {
        // h0 for batch b
        int b = cta - 64;
        float* xs = sh;
        xs[t]       = x[b * IND + t];
        xs[t + 256] = x[b * IND + 256 + t];
        __syncthreads();
        float acc = be[t];
        #pragma unroll 8
        for (int k = 0; k < IND; k++) acc += xs[k] * We[k * H + t];
        for (int r = 0; r < R; r++) hb[(b * R + r) * H + t] = acc;
    } else if (cta < 75) {
        // c2[l] = msg_b2[l] @ upd_W1b[l]
        int l = cta - 72;
        float* bs = sh;
        bs[t] = msg_b2[l * H + t];
        __syncthreads();
        const float* W = upd_W1 + l * 2 * HH + HH;
        float acc = 0.f;
        #pragma unroll 8
        for (int k = 0; k < H; k++) acc += bs[k] * W[k * H + t];
        c2b[l * H + t] = acc;
    }
    gen++; gsync(gen);

    // ---------------- Layers ----------------
    for (int l = 0; l < L; l++) {
        const float* W1a = msg_W1 + l * 2 * HH;
        const float* W1b = W1a + HH;

        // fused-3 GEMM: aact = h@W1a ; bb = h@W1b + b1 ; hu = h@Wu1a + b1u + rs*c2
        if (cta < 192) {
            int job = cta >> 6, rem = cta & 63;
            int m0 = (rem >> 2) * 64, n0 = (rem & 3) * 64;
            if (job == 0)
                gemm_tile(hb, W1a, nullptr, nullptr, nullptr, nullptr, aact, 0, m0, n0, sh);
            else if (job == 1)
                gemm_tile(hb, W1b, msg_b1 + l * H, nullptr, nullptr, nullptr, bbb, 0, m0, n0, sh);
            else
                gemm_tile(hb, upd_W1 + l * 2 * HH, upd_b1 + l * H, rsb, c2b + l * H,
                          nullptr, hub, 0, m0, n0, sh);
        }
        gen++; gsync(gen);

        // agg: 256 items (b=cta>>5, ic=(cta>>3)&3, hc=cta&7)
        {
            int b = cta >> 5, ic = (cta >> 3) & 3, hc = cta & 7;
            float* bbs = sh;          // [128][32]
            float* aS  = sh + 4096;   // [32][129]
            const float* bp = bbb + b * R * H + hc * 32;
            for (int idx = t; idx < 1024; idx += 256) {
                int row = idx >> 3, c4 = (idx & 7) * 4;
                *(float4*)&bbs[row * 32 + c4] = *(const float4*)&bp[row * H + c4];
            }
            for (int idx = t; idx < 1024; idx += 256) {
                int r = idx >> 5, c4 = (idx & 31) * 4;
                float4 av4 = *(const float4*)&Ab[(ic * 32 + r) * R + c4];
                aS[r * 129 + c4 + 0] = av4.x; aS[r * 129 + c4 + 1] = av4.y;
                aS[r * 129 + c4 + 2] = av4.z; aS[r * 129 + c4 + 3] = av4.w;
            }
            __syncthreads();
            int i = t >> 3;            // 0..31
            int c4 = (t & 7) * 4;      // 0..28
            float4 av = *(const float4*)&aact[(b * R + ic * 32 + i) * H + hc * 32 + c4];
            float4 acc = make_float4(0.f, 0.f, 0.f, 0.f);
            const float* ar = &aS[i * 129];
            #pragma unroll 4
            for (int j = 0; j < R; j++) {
                float w = ar[j];
                float4 bv = *(const float4*)&bbs[j * 32 + c4];
                acc.x += w * fmaxf(av.x + bv.x, 0.f);
                acc.y += w * fmaxf(av.y + bv.y, 0.f);
                acc.z += w * fmaxf(av.z + bv.z, 0.f);
                acc.w += w * fmaxf(av.w + bv.w, 0.f);
            }
            *(float4*)&aggb[(b * R + ic * 32 + i) * H + hc * 32 + c4] = acc;
        }
        gen++; gsync(gen);

        // upre = relu(agg@W2u + hu) : 64 tiles
        if (cta < 64) {
            int m0 = (cta >> 2) * 64, n0 = (cta & 3) * 64;
            gemm_tile(aggb, w2ub + l * HH, nullptr, nullptr, nullptr, hub, upreb, 1, m0, n0, sh);
        }
        gen++; gsync(gen);

        // u = upre@Wu2 + b2u : 64 tiles
        if (cta < 64) {
            int m0 = (cta >> 2) * 64, n0 = (cta & 3) * 64;
            gemm_tile(upreb, upd_W2 + l * HH, upd_b2 + l * H, nullptr, nullptr,
                      nullptr, ub, 0, m0, n0, sh);
        }
        gen++; gsync(gen);

        // layernorm: warp per row, 128 CTAs x 8 warps
        if (cta < 128) {
            int row = cta * 8 + wid;
            const float* hp = hb + row * H;
            const float* up = ub + row * H;
            int c8 = lane * 8;
            float v[8];
            {
                float4 h0 = *(const float4*)&hp[c8];
                float4 h1 = *(const float4*)&hp[c8 + 4];
                float4 u0 = *(const float4*)&up[c8];
                float4 u1 = *(const float4*)&up[c8 + 4];
                v[0] = h0.x + u0.x; v[1] = h0.y + u0.y; v[2] = h0.z + u0.z; v[3] = h0.w + u0.w;
                v[4] = h1.x + u1.x; v[5] = h1.y + u1.y; v[6] = h1.z + u1.z; v[7] = h1.w + u1.w;
            }
            float s = 0.f;
            #pragma unroll
            for (int k = 0; k < 8; k++) s += v[k];
            for (int o = 16; o; o >>= 1) s += __shfl_xor_sync(0xffffffffu, s, o);
            float mu = s * (1.f / H);
            float q = 0.f;
            #pragma unroll
            for (int k = 0; k < 8; k++) { float d = v[k] - mu; q += d * d; }
            for (int o = 16; o; o >>= 1) q += __shfl_xor_sync(0xffffffffu, q, o);
            float inv = rsqrtf(q * (1.f / H) + 1e-5f);
            const float* gg = ln_g + l * H;
            const float* bbeta = ln_b + l * H;
            float* hw = hb + row * H;
            #pragma unroll
            for (int k = 0; k < 8; k++)
                hw[c8 + k] = (v[k] - mu) * inv * gg[c8 + k] + bbeta[c8 + k];
        }
        gen++; gsync(gen);
    }

    // ---------------- QKV ----------------
    if (cta < 192) {
        int job = cta >> 6, rem = cta & 63;
        int m0 = (rem >> 2) * 64, n0 = (rem & 3) * 64;
        if (job == 0)      gemm_tile(hb, Wq, bq, nullptr, nullptr, nullptr, qb, 0, m0, n0, sh);
        else if (job == 1) gemm_tile(hb, Wk, bk, nullptr, nullptr, nullptr, kb, 0, m0, n0, sh);
        else               gemm_tile(hb, Wv, bv, nullptr, nullptr, nullptr, vb, 0, m0, n0, sh);
    }
    gen++; gsync(gen);

    // ---------------- Attention: 256 items ----------------
    {
        float* ks = sh;            // 128*65
        float* qs = sh + 8320;     // 16*64
        float* ls = sh + 9344;     // 16*128
        int b = cta >> 5, head = (cta >> 3) & 3, qc = cta & 7;

        const float* kp = kb + b * R * H + head * DH;
        for (int idx = t; idx < 128 * 64; idx += 256) {
            int j = idx >> 6, d = idx & 63;
            ks[j * 65 + d] = kp[j * H + d];
        }
        const float* qp = qb + (b * R + qc * 16) * H + head * DH;
        for (int idx = t; idx < 16 * 64; idx += 256) {
            int r = idx >> 6, d = idx & 63;
            qs[r * 64 + d] = qp[r * H + d];
        }
        __syncthreads();

        {   // logits
            int j = t & 127, g = t >> 7;
            float acc[8];
            #pragma unroll
            for (int r = 0; r < 8; r++) acc[r] = 0.f;
            for (int d = 0; d < 64; d++) {
                float kv = ks[j * 65 + d];
                #pragma unroll
                for (int r = 0; r < 8; r++) acc[r] += qs[(g * 8 + r) * 64 + d] * kv;
            }
            #pragma unroll
            for (int r = 0; r < 8; r++) ls[(g * 8 + r) * 128 + j] = acc[r] * 0.125f;
        }
        __syncthreads();

        {   // row softmax: 16 lanes per row
            int qr = t >> 4, jc = t & 15;
            float e[8]; float mx = -3e38f;
            #pragma unroll
            for (int jj = 0; jj < 8; jj++) {
                e[jj] = ls[qr * 128 + jc * 8 + jj];
                mx = fmaxf(mx, e[jj]);
            }
            for (int o = 8; o; o >>= 1) mx = fmaxf(mx, __shfl_xor_sync(0xffffffffu, mx, o));
            float s = 0.f;
            #pragma unroll
            for (int jj = 0; jj < 8; jj++) { e[jj] = expf(e[jj] - mx); s += e[jj]; }
            for (int o = 8; o; o >>= 1) s += __shfl_xor_sync(0xffffffffu, s, o);
            float inv = 1.f / s;
            #pragma unroll
            for (int jj = 0; jj < 8; jj++) ls[qr * 128 + jc * 8 + jj] = e[jj] * inv;
        }
        float* vs = ks;   // reuse, pitch 64
        const float* vp = vb + b * R * H + head * DH;
        for (int idx = t; idx < 128 * 64; idx += 256) {
            int j = idx >> 6, d = idx & 63;
            vs[j * 64 + d] = vp[j * H + d];
        }
        __syncthreads();

        {   // out = P @ V
            int qr = t >> 4, d4 = (t & 15) * 4;
            float4 acc = make_float4(0.f, 0.f, 0.f, 0.f);
            for (int j = 0; j < 128; j++) {
                float p = ls[qr * 128 + j];
                float4 vv = *(const float4*)&vs[j * 64 + d4];
                acc.x += p * vv.x; acc.y += p * vv.y;
                acc.z += p * vv.z; acc.w += p * vv.w;
            }
            *(float4*)&aob[(b * R + qc * 16 + qr) * H + head * DH + d4] = acc;
        }
    }
    gen++; gsync(gen);

    // ---------------- Readout: 8 items ----------------
    if (cta < 8) {
        float* s0 = sh;
        float* s1 = sh + 256;
        float* red = sh + 512;
        int b = cta;
        {
            float s = 0.f;
            const float* ap = aob + b * R * H + t;
            for (int r = 0; r < R; r++) s += ap[r * H];
            s0[t] = s * (1.f / R);
        }
        __syncthreads();
        float acc = bo[t];
        #pragma unroll 8
        for (int k = 0; k < H; k++) acc += s0[k] * Wo[k * H + t];
        s1[t] = acc;
        __syncthreads();
        acc = rob1[t];
        #pragma unroll 8
        for (int k = 0; k < H; k++) acc += s1[k] * roW1[k * H + t];
        __syncthreads();
        s0[t] = fmaxf(acc, 0.f);
        __syncthreads();
        float lg = -3e38f;
        if (t < R) {
            lg = rob2[t];
            #pragma unroll 8
            for (int k = 0; k < H; k++) lg += s0[k] * roW2[k * R + t];
        }
        float m = lg;
        for (int k = 16; k; k >>= 1) m = fmaxf(m, __shfl_xor_sync(0xffffffffu, m, k));
        if (lane == 0) red[wid] = m;
        __syncthreads();
        if (t < 32) {
            float v = (t < 8) ? red[t] : -3e38f;
            for (int k = 4; k; k >>= 1) v = fmaxf(v, __shfl_xor_sync(0xffffffffu, v, k));
            if (t == 0) red[0] = v;
        }
        __syncthreads();
        float mx = red[0];
        __syncthreads();
        float e = (t < R) ? expf(lg - mx) : 0.f;
        float s = e;
        for (int k = 16; k; k >>= 1) s += __shfl_xor_sync(0xffffffffu, s, k);
        if (lane == 0) red[wid] = s;
        __syncthreads();
        if (t < 32) {
            float v = (t < 8) ? red[t] : 0.f;
            for (int k = 4; k; k >>= 1) v += __shfl_xor_sync(0xffffffffu, v, k);
            if (t == 0) red[0] = v;
        }
        __syncthreads();
        float sum = red[0];
        if (t < R) out[b * R + t] = e / sum;
    }
}

// ---------------------------------------------------------------------------
extern "C" void kernel_launch(void* const* d_in, const int* in_sizes, int n_in,
                              void* d_out, int out_size) {
    mega_kernel<<<NCTA, 256>>>(
        (const float*)d_in[0],  (const float*)d_in[1],  (const float*)d_in[2],
        (const float*)d_in[3],  (const float*)d_in[4],  (const float*)d_in[5],
        (const float*)d_in[6],  (const float*)d_in[7],  (const float*)d_in[8],
        (const float*)d_in[9],  (const float*)d_in[10], (const float*)d_in[11],
        (const float*)d_in[12], (const float*)d_in[13], (const float*)d_in[14],
        (const float*)d_in[15], (const float*)d_in[16], (const float*)d_in[17],
        (const float*)d_in[18], (const float*)d_in[19], (const float*)d_in[20],
        (const float*)d_in[21], (const float*)d_in[22], (const float*)d_in[23],
        (const float*)d_in[24], (const float*)d_in[25], (float*)d_out);
    (void)in_sizes; (void)n_in; (void)out_size;
}

// round 7
// speedup vs baseline: 1.0168x; 1.0168x over previous
#include <cuda_runtime.h>
#include <math.h>

// Problem constants
constexpr int B   = 8;
constexpr int R   = 128;
constexpr int H   = 256;
constexpr int IND = 512;
constexpr int L   = 3;
constexpr int NH  = 4;
constexpr int DH  = 64;

constexpr int SZ = B * R * H;  // 262144
constexpr int HH = H * H;

// Scratch layout
constexpr int OFF_H    = 0;
constexpr int OFF_AACT = SZ;
constexpr int OFF_BB   = 2 * SZ;
constexpr int OFF_AGG  = 3 * SZ;
constexpr int OFF_HU   = 4 * SZ;
constexpr int OFF_UPRE = 5 * SZ;
constexpr int OFF_U    = 6 * SZ;
constexpr int OFF_Q    = 7 * SZ;
constexpr int OFF_K    = 8 * SZ;
constexpr int OFF_V    = 9 * SZ;
constexpr int OFF_AO   = 10 * SZ;
constexpr int OFF_ADJ  = 11 * SZ;                 // R*R
constexpr int OFF_RS   = OFF_ADJ + R * R;         // R
constexpr int OFF_W2U  = OFF_RS + R;              // L*H*H
constexpr int OFF_C2   = OFF_W2U + L * HH;        // L*H
constexpr int TOTAL    = OFF_C2 + L * H;

__device__ float g_buf[TOTAL];

typedef unsigned long long u64;

__device__ __forceinline__ u64 pack2(float x) {
    u64 r; asm("mov.b64 %0, {%1, %1};" : "=l"(r) : "f"(x)); return r;
}
__device__ __forceinline__ void fma2(u64& d, u64 a, u64 b) {
    asm("fma.rn.f32x2 %0, %1, %2, %0;" : "+l"(d) : "l"(a), "l"(b));
}
__device__ __forceinline__ float2 unpack2(u64 v) {
    float2 f; asm("mov.b64 {%0, %1}, %2;" : "=f"(f.x), "=f"(f.y) : "l"(v)); return f;
}

struct GemmJob {
    const float* A;
    const float* W;
    const float* bias;    // [256] or null
    const float* rowv;    // [128] or null (indexed m & 127)
    const float* colv;    // [256] (with rowv)
    const float* addend;  // [M,256] or null
    float* C;
    int relu;
};

// ---------------------------------------------------------------------------
// One BMx64 tile of C = act(A@W [+addend] [+bias] [+rowv*colv]). K = 256 fixed.
// 256 threads, BK=32 double-buffered, fma.rn.f32x2 accumulation (bit-identical
// rounding to scalar FFMA). BM in {32, 64}.
template<int BM>
__device__ __forceinline__ void gemm_tile_dev(const GemmJob& job, int m0, int n0, float* sh) {
    constexpr int RPT = BM / 32;       // rows per thread
    constexpr int APAD = BM + 4;
    float* As = sh;                    // [2][32][APAD], As[buf][k][m]
    float* Ws = sh + 2 * 32 * APAD;    // [2][32][64]

    const float* __restrict__ A = job.A;
    const float* __restrict__ W = job.W;
    const int t = threadIdx.x;
    const int mg = (t >> 3) * RPT;
    const int ng = (t & 7) * 8;
    const int wr = t >> 4, wc = (t & 15) * 4;
    const int ar = (BM == 64) ? (t >> 2) : (t >> 3);
    const int ac = (BM == 64) ? ((t & 3) * 4) : ((t & 7) * 4);

    u64 acc[RPT][4];
    #pragma unroll
    for (int r = 0; r < RPT; r++)
        #pragma unroll
        for (int i = 0; i < 4; i++) acc[r][i] = 0ull;

    const float* Aptr = A + (m0 + ar) * 256 + ac;
    const float* Wptr = W + wr * 256 + n0 + wc;

    float4 aR0, aR1, wR0, wR1;
    aR0 = *(const float4*)Aptr;
    if (BM == 64) aR1 = *(const float4*)(Aptr + 16);
    wR0 = *(const float4*)Wptr;
    wR1 = *(const float4*)(Wptr + 16 * 256);
    {
        float* a0 = As;
        a0[(ac + 0) * APAD + ar] = aR0.x; a0[(ac + 1) * APAD + ar] = aR0.y;
        a0[(ac + 2) * APAD + ar] = aR0.z; a0[(ac + 3) * APAD + ar] = aR0.w;
        if (BM == 64) {
            a0[(ac + 16) * APAD + ar] = aR1.x; a0[(ac + 17) * APAD + ar] = aR1.y;
            a0[(ac + 18) * APAD + ar] = aR1.z; a0[(ac + 19) * APAD + ar] = aR1.w;
        }
        *(float4*)(Ws + wr * 64 + wc) = wR0;
        *(float4*)(Ws + (wr + 16) * 64 + wc) = wR1;
    }
    __syncthreads();

    #pragma unroll 1
    for (int kt = 0; kt < 8; kt++) {
        const int cur = kt & 1;
        if (kt < 7) {
            const int k0 = (kt + 1) * 32;
            aR0 = *(const float4*)(Aptr + k0);
            if (BM == 64) aR1 = *(const float4*)(Aptr + k0 + 16);
            wR0 = *(const float4*)(Wptr + k0 * 256);
            wR1 = *(const float4*)(Wptr + (k0 + 16) * 256);
        }
        const float* as = As + cur * 32 * APAD;
        const float* ws = Ws + cur * 2048;
        #pragma unroll
        for (int kk = 0; kk < 32; kk++) {
            ulonglong2 w0 = *(const ulonglong2*)(ws + kk * 64 + ng);
            ulonglong2 w1 = *(const ulonglong2*)(ws + kk * 64 + ng + 4);
            if (RPT == 2) {
                float2 av = *(const float2*)(as + kk * APAD + mg);
                u64 p0 = pack2(av.x), p1 = pack2(av.y);
                fma2(acc[0][0], p0, w0.x); fma2(acc[0][1], p0, w0.y);
                fma2(acc[0][2], p0, w1.x); fma2(acc[0][3], p0, w1.y);
                fma2(acc[1][0], p1, w0.x); fma2(acc[1][1], p1, w0.y);
                fma2(acc[1][2], p1, w1.x); fma2(acc[1][3], p1, w1.y);
            } else {
                u64 p0 = pack2(as[kk * APAD + mg]);
                fma2(acc[0][0], p0, w0.x); fma2(acc[0][1], p0, w0.y);
                fma2(acc[0][2], p0, w1.x); fma2(acc[0][3], p0, w1.y);
            }
        }
        if (kt < 7) {
            float* a1 = As + (cur ^ 1) * 32 * APAD;
            a1[(ac + 0) * APAD + ar] = aR0.x; a1[(ac + 1) * APAD + ar] = aR0.y;
            a1[(ac + 2) * APAD + ar] = aR0.z; a1[(ac + 3) * APAD + ar] = aR0.w;
            if (BM == 64) {
                a1[(ac + 16) * APAD + ar] = aR1.x; a1[(ac + 17) * APAD + ar] = aR1.y;
                a1[(ac + 18) * APAD + ar] = aR1.z; a1[(ac + 19) * APAD + ar] = aR1.w;
            }
            float* w1p = Ws + (cur ^ 1) * 2048;
            *(float4*)(w1p + wr * 64 + wc) = wR0;
            *(float4*)(w1p + (wr + 16) * 64 + wc) = wR1;
        }
        __syncthreads();
    }

    float4 bi0, bi1, cv0, cv1;
    if (job.bias) {
        bi0 = *(const float4*)&job.bias[n0 + ng];
        bi1 = *(const float4*)&job.bias[n0 + ng + 4];
    }
    if (job.rowv) {
        cv0 = *(const float4*)&job.colv[n0 + ng];
        cv1 = *(const float4*)&job.colv[n0 + ng + 4];
    }
    #pragma unroll
    for (int r = 0; r < RPT; r++) {
        const int m = m0 + mg + r;
        float2 q0 = unpack2(acc[r][0]);
        float2 q1 = unpack2(acc[r][1]);
        float2 q2 = unpack2(acc[r][2]);
        float2 q3 = unpack2(acc[r][3]);
        float4 v0 = make_float4(q0.x, q0.y, q1.x, q1.y);
        float4 v1 = make_float4(q2.x, q2.y, q3.x, q3.y);
        if (job.addend) {
            float4 a0 = *(const float4*)&job.addend[m * 256 + n0 + ng];
            float4 a1 = *(const float4*)&job.addend[m * 256 + n0 + ng + 4];
            v0.x += a0.x; v0.y += a0.y; v0.z += a0.z; v0.w += a0.w;
            v1.x += a1.x; v1.y += a1.y; v1.z += a1.z; v1.w += a1.w;
        }
        if (job.bias) {
            v0.x += bi0.x; v0.y += bi0.y; v0.z += bi0.z; v0.w += bi0.w;
            v1.x += bi1.x; v1.y += bi1.y; v1.z += bi1.z; v1.w += bi1.w;
        }
        if (job.rowv) {
            float rv = job.rowv[m & (R - 1)];
            v0.x += rv * cv0.x; v0.y += rv * cv0.y; v0.z += rv * cv0.z; v0.w += rv * cv0.w;
            v1.x += rv * cv1.x; v1.y += rv * cv1.y; v1.z += rv * cv1.z; v1.w += rv * cv1.w;
        }
        if (job.relu) {
            v0.x = fmaxf(v0.x, 0.f); v0.y = fmaxf(v0.y, 0.f);
            v0.z = fmaxf(v0.z, 0.f); v0.w = fmaxf(v0.w, 0.f);
            v1.x = fmaxf(v1.x, 0.f); v1.y = fmaxf(v1.y, 0.f);
            v1.z = fmaxf(v1.z, 0.f); v1.w = fmaxf(v1.w, 0.f);
        }
        *(float4*)&job.C[m * 256 + n0 + ng] = v0;
        *(float4*)&job.C[m * 256 + n0 + ng + 4] = v1;
    }
}

// sh size needed for BM=64: 2*32*68 + 2*32*64 = 8448 floats
constexpr int GEMM_SH64 = 2 * 32 * 68 + 2 * 32 * 64;

template<int BM>
__global__ __launch_bounds__(256, 2) void gemm_kernel(GemmJob j0, GemmJob j1, GemmJob j2) {
    __shared__ float sh[GEMM_SH64];
    const GemmJob& job = (blockIdx.z == 0) ? j0 : ((blockIdx.z == 1) ? j1 : j2);
    gemm_tile_dev<BM>(job, blockIdx.y * BM, blockIdx.x * 64, sh);
}

// ---------------------------------------------------------------------------
// Setup: blocks 0..47 -> W2u tiles ; 48..63 -> prep_A ; 64..71 -> h0 ; 72..74 -> c2
__global__ __launch_bounds__(256, 2) void setup_kernel(
    const float* __restrict__ rule_adj, float* __restrict__ A, float* __restrict__ rowsum,
    const float* __restrict__ x, const float* __restrict__ We,
    const float* __restrict__ be, float* __restrict__ h,
    const float* __restrict__ msg_b2, const float* __restrict__ msg_W2,
    const float* __restrict__ upd_W1, float* __restrict__ w2u, float* __restrict__ c2)
{
    __shared__ float sh[GEMM_SH64];
    int bid = blockIdx.x, t = threadIdx.x;
    if (bid < 48) {
        // W2u[l] = msg_W2[l] @ upd_W1b[l] ; 16 tiles (4x4) per l
        int l = bid >> 4, rem = bid & 15;
        GemmJob j;
        j.A = msg_W2 + l * HH; j.W = upd_W1 + l * 2 * HH + HH;
        j.bias = nullptr; j.rowv = nullptr; j.colv = nullptr; j.addend = nullptr;
        j.C = w2u + l * HH; j.relu = 0;
        gemm_tile_dev<64>(j, (rem >> 2) * 64, (rem & 3) * 64, sh);
    } else if (bid < 64) {
        // prep_A: warp per row
        int wid = t >> 5, lane = t & 31;
        int i = (bid - 48) * 8 + wid;
        float4 va = *(const float4*)&rule_adj[i * R + lane * 4];
        float s0 = 1.f / (1.f + expf(-va.x));
        float s1 = 1.f / (1.f + expf(-va.y));
        float s2 = 1.f / (1.f + expf(-va.z));
        float s3 = 1.f / (1.f + expf(-va.w));
        int c = lane * 4;
        if (i == c + 0) s0 = 0.f;
        if (i == c + 1) s1 = 0.f;
        if (i == c + 2) s2 = 0.f;
        if (i == c + 3) s3 = 0.f;
        *(float4*)&A[i * R + c] = make_float4(s0, s1, s2, s3);
        float part = s0 + s1 + s2 + s3;
        for (int o = 16; o; o >>= 1) part += __shfl_xor_sync(0xffffffffu, part, o);
        if (lane == 0) rowsum[i] = part;
    } else if (bid < 72) {
        // h0 for batch b
        int b = bid - 64;
        float* xs = sh;
        xs[t]       = x[b * IND + t];
        xs[t + 256] = x[b * IND + 256 + t];
        __syncthreads();
        float acc = be[t];
        #pragma unroll 8
        for (int k = 0; k < IND; k++) acc += xs[k] * We[k * H + t];
        for (int r = 0; r < R; r++) h[(b * R + r) * H + t] = acc;
    } else {
        // c2[l] = msg_b2[l] @ upd_W1b[l]
        int l = bid - 72;
        float* bs = sh;
        bs[t] = msg_b2[l * H + t];
        __syncthreads();
        const float* W = upd_W1 + l * 2 * HH + HH;
        float acc = 0.f;
        #pragma unroll 8
        for (int k = 0; k < H; k++) acc += bs[k] * W[k * H + t];
        c2[l * H + t] = acc;
    }
}

// ---------------------------------------------------------------------------
// aggpre[b,i,h] = sum_j A[i,j] * relu(a[b,i,h] + bb[b,j,h])   (b1 folded into bb)
// grid (hc=4, ic=4, b=8) = 128 CTAs, 256 threads. (round-2 proven version)
__global__ __launch_bounds__(256) void agg_kernel(
    const float* __restrict__ a, const float* __restrict__ bbg,
    const float* __restrict__ A, float* __restrict__ out)
{
    __shared__ float bbs[128 * 64];
    int hc = blockIdx.x * 64, ic = blockIdx.y * 32, b = blockIdx.z;
    int t = threadIdx.x;
    const float* bp = bbg + b * R * H;
    for (int idx = t; idx < 2048; idx += 256) {
        int j = idx >> 4, c4 = (idx & 15) * 4;
        *(float4*)&bbs[j * 64 + c4] = *(const float4*)&bp[j * H + hc + c4];
    }
    __syncthreads();
    int hl = (t & 15) * 4;
    int i0 = ic + (t >> 4) * 2;
    float4 av0 = *(const float4*)&a[(b * R + i0) * H + hc + hl];
    float4 av1 = *(const float4*)&a[(b * R + i0 + 1) * H + hc + hl];
    float4 ac0 = {0, 0, 0, 0}, ac1 = {0, 0, 0, 0};
    const float* Ar = A + i0 * R;
    #pragma unroll 4
    for (int j = 0; j < R; j++) {
        float4 bv = *(const float4*)&bbs[j * 64 + hl];
        float w0 = __ldg(&Ar[j]);
        float w1 = __ldg(&Ar[R + j]);
        ac0.x += w0 * fmaxf(av0.x + bv.x, 0.f);
        ac0.y += w0 * fmaxf(av0.y + bv.y, 0.f);
        ac0.z += w0 * fmaxf(av0.z + bv.z, 0.f);
        ac0.w += w0 * fmaxf(av0.w + bv.w, 0.f);
        ac1.x += w1 * fmaxf(av1.x + bv.x, 0.f);
        ac1.y += w1 * fmaxf(av1.y + bv.y, 0.f);
        ac1.z += w1 * fmaxf(av1.z + bv.z, 0.f);
        ac1.w += w1 * fmaxf(av1.w + bv.w, 0.f);
    }
    *(float4*)&out[(b * R + i0) * H + hc + hl]     = ac0;
    *(float4*)&out[(b * R + i0 + 1) * H + hc + hl] = ac1;
}

// ---------------------------------------------------------------------------
// h = LayerNorm(h + u) * g + beta
__global__ void ln_kernel(float* __restrict__ h, const float* __restrict__ u,
                          const float* __restrict__ gg, const float* __restrict__ bb) {
    __shared__ float red[8];
    int row = blockIdx.x, t = threadIdx.x;
    int o = row * H + t;
    float x = h[o] + u[o];
    float s = x;
    for (int k = 16; k; k >>= 1) s += __shfl_xor_sync(0xffffffffu, s, k);
    if ((t & 31) == 0) red[t >> 5] = s;
    __syncthreads();
    if (t < 32) {
        float v = (t < 8) ? red[t] : 0.f;
        for (int k = 4; k; k >>= 1) v += __shfl_xor_sync(0xffffffffu, v, k);
        if (t == 0) red[0] = v;
    }
    __syncthreads();
    float mu = red[0] * (1.f / H);
    __syncthreads();
    float d = x - mu;
    float q = d * d;
    for (int k = 16; k; k >>= 1) q += __shfl_xor_sync(0xffffffffu, q, k);
    if ((t & 31) == 0) red[t >> 5] = q;
    __syncthreads();
    if (t < 32) {
        float v = (t < 8) ? red[t] : 0.f;
        for (int k = 4; k; k >>= 1) v += __shfl_xor_sync(0xffffffffu, v, k);
        if (t == 0) red[0] = v;
    }
    __syncthreads();
    float var = red[0] * (1.f / H);
    h[o] = d * rsqrtf(var + 1e-5f) * gg[t] + bb[t];
}

// ---------------------------------------------------------------------------
// Multi-head attention for one (b, head, q-chunk of 16 rows).
__global__ __launch_bounds__(256) void attn_kernel(
    const float* __restrict__ q, const float* __restrict__ k,
    const float* __restrict__ v, float* __restrict__ ao)
{
    __shared__ float ks[128 * 65];
    __shared__ float qs[16 * 64];
    __shared__ float ls[16 * 128];
    int qc = blockIdx.x, head = blockIdx.y, b = blockIdx.z;
    int t = threadIdx.x;

    const float* kb = k + b * R * H + head * DH;
    for (int idx = t; idx < 128 * 64; idx += 256) {
        int j = idx >> 6, d = idx & 63;
        ks[j * 65 + d] = kb[j * H + d];
    }
    const float* qb = q + (b * R + qc * 16) * H + head * DH;
    for (int idx = t; idx < 16 * 64; idx += 256) {
        int r = idx >> 6, d = idx & 63;
        qs[r * 64 + d] = qb[r * H + d];
    }
    __syncthreads();

    {   // logits
        int j = t & 127, g = t >> 7;
        float acc[8];
        #pragma unroll
        for (int r = 0; r < 8; r++) acc[r] = 0.f;
        for (int d = 0; d < 64; d++) {
            float kv = ks[j * 65 + d];
            #pragma unroll
            for (int r = 0; r < 8; r++) acc[r] += qs[(g * 8 + r) * 64 + d] * kv;
        }
        #pragma unroll
        for (int r = 0; r < 8; r++) ls[(g * 8 + r) * 128 + j] = acc[r] * 0.125f;
    }
    __syncthreads();

    {   // row softmax
        int qr = t >> 4, jc = t & 15;
        float e[8]; float mx = -3e38f;
        #pragma unroll
        for (int jj = 0; jj < 8; jj++) {
            e[jj] = ls[qr * 128 + jc * 8 + jj];
            mx = fmaxf(mx, e[jj]);
        }
        for (int o = 8; o; o >>= 1) mx = fmaxf(mx, __shfl_xor_sync(0xffffffffu, mx, o));
        float s = 0.f;
        #pragma unroll
        for (int jj = 0; jj < 8; jj++) { e[jj] = expf(e[jj] - mx); s += e[jj]; }
        for (int o = 8; o; o >>= 1) s += __shfl_xor_sync(0xffffffffu, s, o);
        float inv = 1.f / s;
        #pragma unroll
        for (int jj = 0; jj < 8; jj++) ls[qr * 128 + jc * 8 + jj] = e[jj] * inv;
    }
    float* vs = ks;
    const float* vb = v + b * R * H + head * DH;
    for (int idx = t; idx < 128 * 64; idx += 256) {
        int j = idx >> 6, d = idx & 63;
        vs[j * 64 + d] = vb[j * H + d];
    }
    __syncthreads();

    {   // out = P @ V
        int qr = t >> 4, d4 = (t & 15) * 4;
        float4 acc = {0, 0, 0, 0};
        for (int j = 0; j < 128; j++) {
            float p = ls[qr * 128 + j];
            float4 vv = *(const float4*)&vs[j * 64 + d4];
            acc.x += p * vv.x; acc.y += p * vv.y;
            acc.z += p * vv.z; acc.w += p * vv.w;
        }
        *(float4*)&ao[(b * R + qc * 16 + qr) * H + head * DH + d4] = acc;
    }
}

// ---------------------------------------------------------------------------
// abar = mean_r ao; g = abar@Wo + bo; t = relu(g@roW1+rob1); logits; softmax.
__global__ void readout_kernel(const float* __restrict__ ao,
                               const float* __restrict__ Wo, const float* __restrict__ bo,
                               const float* __restrict__ roW1, const float* __restrict__ rob1,
                               const float* __restrict__ roW2, const float* __restrict__ rob2,
                               float* __restrict__ out) {
    __shared__ float s0[H], s1[H];
    __shared__ float red[8];
    int b = blockIdx.x, t = threadIdx.x;
    {
        float s = 0.f;
        const float* ap = ao + b * R * H + t;
        for (int r = 0; r < R; r++) s += ap[r * H];
        s0[t] = s * (1.f / R);
    }
    __syncthreads();
    float acc = bo[t];
    #pragma unroll 8
    for (int k = 0; k < H; k++) acc += s0[k] * Wo[k * H + t];
    s1[t] = acc;
    __syncthreads();
    acc = rob1[t];
    #pragma unroll 8
    for (int k = 0; k < H; k++) acc += s1[k] * roW1[k * H + t];
    __syncthreads();
    s0[t] = fmaxf(acc, 0.f);
    __syncthreads();
    float lg = -3e38f;
    if (t < R) {
        lg = rob2[t];
        #pragma unroll 8
        for (int k = 0; k < H; k++) lg += s0[k] * roW2[k * R + t];
    }
    float m = lg;
    for (int k = 16; k; k >>= 1) m = fmaxf(m, __shfl_xor_sync(0xffffffffu, m, k));
    if ((t & 31) == 0) red[t >> 5] = m;
    __syncthreads();
    if (t < 32) {
        float v = (t < 8) ? red[t] : -3e38f;
        for (int k = 4; k; k >>= 1) v = fmaxf(v, __shfl_xor_sync(0xffffffffu, v, k));
        if (t == 0) red[0] = v;
    }
    __syncthreads();
    float mx = red[0];
    __syncthreads();
    float e = (t < R) ? expf(lg - mx) : 0.f;
    float s = e;
    for (int k = 16; k; k >>= 1) s += __shfl_xor_sync(0xffffffffu, s, k);
    if ((t & 31) == 0) red[t >> 5] = s;
    __syncthreads();
    if (t < 32) {
        float v = (t < 8) ? red[t] : 0.f;
        for (int k = 4; k; k >>= 1) v += __shfl_xor_sync(0xffffffffu, v, k);
        if (t == 0) red[0] = v;
    }
    __syncthreads();
    float sum = red[0];
    if (t < R) out[b * R + t] = e / sum;
}

// ---------------------------------------------------------------------------
static inline GemmJob mkjob(const float* A, const float* W, float* C,
                            const float* bias = nullptr, const float* rowv = nullptr,
                            const float* colv = nullptr, const float* addend = nullptr,
                            int relu = 0) {
    GemmJob j;
    j.A = A; j.W = W; j.bias = bias; j.rowv = rowv; j.colv = colv;
    j.addend = addend; j.C = C; j.relu = relu;
    return j;
}

extern "C" void kernel_launch(void* const* d_in, const int* in_sizes, int n_in,
                              void* d_out, int out_size) {
    const float* x       = (const float*)d_in[0];
    const float* We      = (const float*)d_in[1];
    const float* be      = (const float*)d_in[2];
    const float* msg_W1  = (const float*)d_in[3];
    const float* msg_b1  = (const float*)d_in[4];
    const float* msg_W2  = (const float*)d_in[5];
    const float* msg_b2  = (const float*)d_in[6];
    const float* upd_W1  = (const float*)d_in[7];
    const float* upd_b1  = (const float*)d_in[8];
    const float* upd_W2  = (const float*)d_in[9];
    const float* upd_b2  = (const float*)d_in[10];
    const float* ln_g    = (const float*)d_in[11];
    const float* ln_b    = (const float*)d_in[12];
    const float* rule_adj= (const float*)d_in[13];
    const float* Wq      = (const float*)d_in[14];
    const float* bq      = (const float*)d_in[15];
    const float* Wk      = (const float*)d_in[16];
    const float* bk      = (const float*)d_in[17];
    const float* Wv      = (const float*)d_in[18];
    const float* bv      = (const float*)d_in[19];
    const float* Wo      = (const float*)d_in[20];
    const float* bo      = (const float*)d_in[21];
    const float* roW1    = (const float*)d_in[22];
    const float* rob1    = (const float*)d_in[23];
    const float* roW2    = (const float*)d_in[24];
    const float* rob2    = (const float*)d_in[25];
    float* out = (float*)d_out;

    float* base = nullptr;
    cudaGetSymbolAddress((void**)&base, g_buf);
    float* hb    = base + OFF_H;
    float* aact  = base + OFF_AACT;
    float* bbb   = base + OFF_BB;
    float* aggb  = base + OFF_AGG;
    float* hub   = base + OFF_HU;
    float* upreb = base + OFF_UPRE;
    float* ub    = base + OFF_U;
    float* qb    = base + OFF_Q;
    float* kb    = base + OFF_K;
    float* vb    = base + OFF_V;
    float* aob   = base + OFF_AO;
    float* Ab    = base + OFF_ADJ;
    float* rsb   = base + OFF_RS;
    float* w2ub  = base + OFF_W2U;
    float* c2b   = base + OFF_C2;

    const int M = B * R;  // 1024
    dim3 g3(4, M / 64, 3);      // fused-3, BM=64 tiles: 192 CTAs
    dim3 g1(4, M / 32, 1);      // single job, BM=32 tiles: 128 CTAs

    setup_kernel<<<75, 256>>>(rule_adj, Ab, rsb, x, We, be, hb,
                              msg_b2, msg_W2, upd_W1, w2ub, c2b);

    for (int l = 0; l < L; l++) {
        const float* W1a = msg_W1 + l * 2 * HH;
        const float* W1b = W1a + HH;
        // fused: aact = h@W1a ; bb = h@W1b + b1 ; hu = h@Wu1a + b1u + rs*c2
        gemm_kernel<64><<<g3, 256>>>(
            mkjob(hb, W1a, aact),
            mkjob(hb, W1b, bbb, msg_b1 + l * H),
            mkjob(hb, upd_W1 + l * 2 * HH, hub, upd_b1 + l * H, rsb, c2b + l * H));
        agg_kernel<<<dim3(4, 4, B), 256>>>(aact, bbb, Ab, aggb);
        // upre = relu(agg@W2u + hu)
        {
            GemmJob j = mkjob(aggb, w2ub + l * HH, upreb, nullptr, nullptr, nullptr, hub, 1);
            gemm_kernel<32><<<g1, 256>>>(j, j, j);
        }
        // u = upre@Wu2 + b2u
        {
            GemmJob j = mkjob(upreb, upd_W2 + l * HH, ub, upd_b2 + l * H);
            gemm_kernel<32><<<g1, 256>>>(j, j, j);
        }
        ln_kernel<<<M, H>>>(hb, ub, ln_g + l * H, ln_b + l * H);
    }

    // fused q/k/v
    gemm_kernel<64><<<g3, 256>>>(
        mkjob(hb, Wq, qb, bq),
        mkjob(hb, Wk, kb, bk),
        mkjob(hb, Wv, vb, bv));
    attn_kernel<<<dim3(R / 16, NH, B), 256>>>(qb, kb, vb, aob);
    readout_kernel<<<B, H>>>(aob, Wo, bo, roW1, rob1, roW2, rob2, out);
    (void)in_sizes; (void)n_in; (void)out_size;
}

// round 8
// speedup vs baseline: 1.4714x; 1.4471x over previous
#include <cuda_runtime.h>
#include <math.h>

// Problem constants
constexpr int B   = 8;
constexpr int R   = 128;
constexpr int H   = 256;
constexpr int IND = 512;
constexpr int L   = 3;
constexpr int NH  = 4;
constexpr int DH  = 64;

constexpr int SZ = B * R * H;  // 262144
constexpr int HH = H * H;

// Scratch layout
constexpr int OFF_H    = 0;
constexpr int OFF_AACT = SZ;
constexpr int OFF_BB   = 2 * SZ;
constexpr int OFF_AGG  = 3 * SZ;
constexpr int OFF_HU   = 4 * SZ;
constexpr int OFF_Q    = 5 * SZ;
constexpr int OFF_K    = 6 * SZ;
constexpr int OFF_V    = 7 * SZ;
constexpr int OFF_AO   = 8 * SZ;
constexpr int OFF_ADJ  = 9 * SZ;                  // R*R
constexpr int OFF_RS   = OFF_ADJ + R * R;         // R
constexpr int OFF_W2U  = OFF_RS + R;              // L*H*H
constexpr int OFF_C2   = OFF_W2U + L * HH;        // L*H
constexpr int TOTAL    = OFF_C2 + L * H;

__device__ float g_buf[TOTAL];

typedef unsigned long long u64;

__device__ __forceinline__ u64 pack2(float x) {
    u64 r; asm("mov.b64 %0, {%1, %1};" : "=l"(r) : "f"(x)); return r;
}
__device__ __forceinline__ void fma2(u64& d, u64 a, u64 b) {
    asm("fma.rn.f32x2 %0, %1, %2, %0;" : "+l"(d) : "l"(a), "l"(b));
}
__device__ __forceinline__ float2 unpack2(u64 v) {
    float2 f; asm("mov.b64 {%0, %1}, %2;" : "=f"(f.x), "=f"(f.y) : "l"(v)); return f;
}

struct GemmJob {
    const float* A;
    const float* W;
    const float* bias;    // [256] or null
    const float* rowv;    // [128] or null (indexed m & 127)
    const float* colv;    // [256] (with rowv)
    const float* addend;  // [M,256] or null
    float* C;
    int relu;
};

// ---------------------------------------------------------------------------
// Round-3 proven GEMM tile as a device function. BM=32, BN=64, BK=32,
// 256 threads, double-buffered, f32x2 accumulation. sh needs 6400 floats.
constexpr int G3_SH = 2 * 32 * 36 + 2 * 32 * 64;  // 6400

__device__ __forceinline__ void g3_tile(const GemmJob& job, int m0, int n0, float* sh) {
    float* AsBuf = sh;             // [2][32*36]
    float* WsBuf = sh + 2 * 32 * 36;

    const float* __restrict__ A = job.A;
    const float* __restrict__ W = job.W;
    const int tid = threadIdx.x;
    const int tx = tid & 15, ty = tid >> 4;

    const int ar = tid >> 3, ac4 = (tid & 7) * 4;
    const int wc0 = tid >> 4, wn0 = (tid & 15) * 4;
    const int wc1 = (tid + 256) >> 4, wn1 = wn0;

    u64 acc[2][2];
    acc[0][0] = acc[0][1] = acc[1][0] = acc[1][1] = 0ull;

    float4 aR = *(const float4*)&A[(m0 + ar) * 256 + ac4];
    float4 wR0 = *(const float4*)&W[wc0 * 256 + n0 + wn0];
    float4 wR1 = *(const float4*)&W[wc1 * 256 + n0 + wn1];
    *(float4*)&AsBuf[ar * 36 + ac4] = aR;
    *(float4*)&WsBuf[wc0 * 64 + wn0] = wR0;
    *(float4*)&WsBuf[wc1 * 64 + wn1] = wR1;
    __syncthreads();

    #pragma unroll 1
    for (int t = 0; t < 8; t++) {
        const int cur = t & 1;
        const bool has_next = (t < 7);
        if (has_next) {
            const int k0 = (t + 1) * 32;
            aR  = *(const float4*)&A[(m0 + ar) * 256 + k0 + ac4];
            wR0 = *(const float4*)&W[(k0 + wc0) * 256 + n0 + wn0];
            wR1 = *(const float4*)&W[(k0 + wc1) * 256 + n0 + wn1];
        }
        const float* __restrict__ as = AsBuf + cur * (32 * 36);
        const float* __restrict__ ws = WsBuf + cur * (32 * 64);
        #pragma unroll
        for (int kk = 0; kk < 32; kk++) {
            ulonglong2 bv = *(const ulonglong2*)&ws[kk * 64 + tx * 4];
            u64 pa0 = pack2(as[(ty * 2 + 0) * 36 + kk]);
            u64 pa1 = pack2(as[(ty * 2 + 1) * 36 + kk]);
            fma2(acc[0][0], pa0, bv.x);
            fma2(acc[0][1], pa0, bv.y);
            fma2(acc[1][0], pa1, bv.x);
            fma2(acc[1][1], pa1, bv.y);
        }
        if (has_next) {
            const int nxt = cur ^ 1;
            *(float4*)&AsBuf[nxt * (32 * 36) + ar * 36 + ac4] = aR;
            *(float4*)&WsBuf[nxt * (32 * 64) + wc0 * 64 + wn0] = wR0;
            *(float4*)&WsBuf[nxt * (32 * 64) + wc1 * 64 + wn1] = wR1;
        }
        __syncthreads();
    }

    const int n = n0 + tx * 4;
    #pragma unroll
    for (int i = 0; i < 2; i++) {
        const int m = m0 + ty * 2 + i;
        float2 p0 = unpack2(acc[i][0]);
        float2 p1 = unpack2(acc[i][1]);
        float4 v = make_float4(p0.x, p0.y, p1.x, p1.y);
        if (job.addend) {
            float4 ad = *(const float4*)&job.addend[m * 256 + n];
            v.x += ad.x; v.y += ad.y; v.z += ad.z; v.w += ad.w;
        }
        if (job.bias) {
            float4 bi = *(const float4*)&job.bias[n];
            v.x += bi.x; v.y += bi.y; v.z += bi.z; v.w += bi.w;
        }
        if (job.rowv) {
            float rv = job.rowv[m & (R - 1)];
            float4 cv = *(const float4*)&job.colv[n];
            v.x += rv * cv.x; v.y += rv * cv.y; v.z += rv * cv.z; v.w += rv * cv.w;
        }
        if (job.relu) {
            v.x = fmaxf(v.x, 0.f); v.y = fmaxf(v.y, 0.f);
            v.z = fmaxf(v.z, 0.f); v.w = fmaxf(v.w, 0.f);
        }
        *(float4*)&job.C[m * 256 + n] = v;
    }
}

__global__ __launch_bounds__(256) void gemm_kernel(GemmJob j0, GemmJob j1, GemmJob j2) {
    __shared__ float sh[G3_SH];
    const GemmJob& job = (blockIdx.z == 0) ? j0 : ((blockIdx.z == 1) ? j1 : j2);
    g3_tile(job, blockIdx.y * 32, blockIdx.x * 64, sh);
}

// ---------------------------------------------------------------------------
// Setup: 0..95 -> W2u tiles ; 96..111 -> prep_A ; 112..119 -> h0 ; 120..122 -> c2
__global__ __launch_bounds__(256) void setup_kernel(
    const float* __restrict__ rule_adj, float* __restrict__ A, float* __restrict__ rowsum,
    const float* __restrict__ x, const float* __restrict__ We,
    const float* __restrict__ be, float* __restrict__ h,
    const float* __restrict__ msg_b2, const float* __restrict__ msg_W2,
    const float* __restrict__ upd_W1, float* __restrict__ w2u, float* __restrict__ c2)
{
    __shared__ float sh[G3_SH];
    int bid = blockIdx.x, t = threadIdx.x;
    if (bid < 96) {
        // W2u[l] = msg_W2[l] @ upd_W1b[l]; 32 tiles (8 m x 4 n) per l
        int l = bid >> 5, rem = bid & 31;
        GemmJob j;
        j.A = msg_W2 + l * HH; j.W = upd_W1 + l * 2 * HH + HH;
        j.bias = nullptr; j.rowv = nullptr; j.colv = nullptr; j.addend = nullptr;
        j.C = w2u + l * HH; j.relu = 0;
        g3_tile(j, (rem >> 2) * 32, (rem & 3) * 64, sh);
    } else if (bid < 112) {
        // prep_A: warp per row
        int wid = t >> 5, lane = t & 31;
        int i = (bid - 96) * 8 + wid;
        float4 va = *(const float4*)&rule_adj[i * R + lane * 4];
        float s0 = 1.f / (1.f + expf(-va.x));
        float s1 = 1.f / (1.f + expf(-va.y));
        float s2 = 1.f / (1.f + expf(-va.z));
        float s3 = 1.f / (1.f + expf(-va.w));
        int c = lane * 4;
        if (i == c + 0) s0 = 0.f;
        if (i == c + 1) s1 = 0.f;
        if (i == c + 2) s2 = 0.f;
        if (i == c + 3) s3 = 0.f;
        *(float4*)&A[i * R + c] = make_float4(s0, s1, s2, s3);
        float part = s0 + s1 + s2 + s3;
        for (int o = 16; o; o >>= 1) part += __shfl_xor_sync(0xffffffffu, part, o);
        if (lane == 0) rowsum[i] = part;
    } else if (bid < 120) {
        // h0 for batch b
        int b = bid - 112;
        float* xs = sh;
        xs[t]       = x[b * IND + t];
        xs[t + 256] = x[b * IND + 256 + t];
        __syncthreads();
        float acc = be[t];
        #pragma unroll 8
        for (int k = 0; k < IND; k++) acc += xs[k] * We[k * H + t];
        for (int r = 0; r < R; r++) h[(b * R + r) * H + t] = acc;
    } else {
        // c2[l] = msg_b2[l] @ upd_W1b[l]
        int l = bid - 120;
        float* bs = sh;
        bs[t] = msg_b2[l * H + t];
        __syncthreads();
        const float* W = upd_W1 + l * 2 * HH + HH;
        float acc = 0.f;
        #pragma unroll 8
        for (int k = 0; k < H; k++) acc += bs[k] * W[k * H + t];
        c2[l * H + t] = acc;
    }
}

// ---------------------------------------------------------------------------
// Tail: per 8-row block: upre = relu(agg@W2u + hu); u = upre@Wu2 + b2u;
// h = LayerNorm(h + u)*g + beta. grid 128, 256 threads.
// Thread tile 4 rows x 2 cols, A reads are warp-broadcast from smem.
constexpr int TBK = 16;
__global__ __launch_bounds__(256) void tail_kernel(
    const float* __restrict__ agg, const float* __restrict__ hu,
    const float* __restrict__ W2u, const float* __restrict__ Wu2,
    const float* __restrict__ b2u, const float* __restrict__ lng,
    const float* __restrict__ lnbeta, float* __restrict__ h)
{
    __shared__ float wt[2][TBK * 256];   // 32 KB
    __shared__ float rb[8 * 256];        // 8 KB
    const int t = threadIdx.x;
    const int m0 = blockIdx.x * 8;

    // fill rb with agg rows
    {
        int r = t >> 5, c = (t & 31) * 8;
        *(float4*)&rb[r * 256 + c]     = *(const float4*)&agg[(m0 + r) * 256 + c];
        *(float4*)&rb[r * 256 + c + 4] = *(const float4*)&agg[(m0 + r) * 256 + c + 4];
    }
    const int col = (t & 127) * 2;      // 2 cols
    const int r0  = (t >> 7) * 4;       // 4 rows
    const int wk  = t >> 4, wn = (t & 15) * 16;   // W tile load map

    float outv[8];

    #pragma unroll 1
    for (int phase = 0; phase < 2; phase++) {
        const float* __restrict__ Wm = (phase == 0) ? W2u : Wu2;
        u64 acc[4];
        acc[0] = acc[1] = acc[2] = acc[3] = 0ull;

        float4 p0 = *(const float4*)&Wm[wk * 256 + wn];
        float4 p1 = *(const float4*)&Wm[wk * 256 + wn + 4];
        float4 p2 = *(const float4*)&Wm[wk * 256 + wn + 8];
        float4 p3 = *(const float4*)&Wm[wk * 256 + wn + 12];
        *(float4*)&wt[0][wk * 256 + wn]      = p0;
        *(float4*)&wt[0][wk * 256 + wn + 4]  = p1;
        *(float4*)&wt[0][wk * 256 + wn + 8]  = p2;
        *(float4*)&wt[0][wk * 256 + wn + 12] = p3;
        __syncthreads();

        #pragma unroll 1
        for (int kt = 0; kt < 256 / TBK; kt++) {
            const int cur = kt & 1;
            if (kt < 256 / TBK - 1) {
                const int krow = (kt + 1) * TBK + wk;
                p0 = *(const float4*)&Wm[krow * 256 + wn];
                p1 = *(const float4*)&Wm[krow * 256 + wn + 4];
                p2 = *(const float4*)&Wm[krow * 256 + wn + 8];
                p3 = *(const float4*)&Wm[krow * 256 + wn + 12];
            }
            const float* __restrict__ wb = wt[cur];
            const int kbase = kt * TBK;
            #pragma unroll
            for (int kk = 0; kk < TBK; kk++) {
                u64 w = *(const u64*)&wb[kk * 256 + col];
                u64 a0 = pack2(rb[(r0 + 0) * 256 + kbase + kk]);
                u64 a1 = pack2(rb[(r0 + 1) * 256 + kbase + kk]);
                u64 a2 = pack2(rb[(r0 + 2) * 256 + kbase + kk]);
                u64 a3 = pack2(rb[(r0 + 3) * 256 + kbase + kk]);
                fma2(acc[0], a0, w);
                fma2(acc[1], a1, w);
                fma2(acc[2], a2, w);
                fma2(acc[3], a3, w);
            }
            if (kt < 256 / TBK - 1) {
                float* wnx = wt[cur ^ 1];
                *(float4*)&wnx[wk * 256 + wn]      = p0;
                *(float4*)&wnx[wk * 256 + wn + 4]  = p1;
                *(float4*)&wnx[wk * 256 + wn + 8]  = p2;
                *(float4*)&wnx[wk * 256 + wn + 12] = p3;
            }
            __syncthreads();
        }

        if (phase == 0) {
            // upre = relu(acc + hu)
            #pragma unroll
            for (int i = 0; i < 4; i++) {
                float2 v = unpack2(acc[i]);
                float2 hv = *(const float2*)&hu[(m0 + r0 + i) * 256 + col];
                outv[i * 2 + 0] = fmaxf(v.x + hv.x, 0.f);
                outv[i * 2 + 1] = fmaxf(v.y + hv.y, 0.f);
            }
        } else {
            // u = acc + b2u
            float2 bv = *(const float2*)&b2u[col];
            #pragma unroll
            for (int i = 0; i < 4; i++) {
                float2 v = unpack2(acc[i]);
                outv[i * 2 + 0] = v.x + bv.x;
                outv[i * 2 + 1] = v.y + bv.y;
            }
        }
        // publish phase result into rb (all reads of rb are complete: last
        // k-tile ended with __syncthreads above)
        #pragma unroll
        for (int i = 0; i < 4; i++)
            *(float2*)&rb[(r0 + i) * 256 + col] = make_float2(outv[i * 2], outv[i * 2 + 1]);
        __syncthreads();
    }

    // LayerNorm: warp per row (8 warps, 8 rows); rb holds u.
    {
        const int wid = t >> 5, lane = t & 31;
        const int row = m0 + wid;
        const int c8 = lane * 8;
        float4 u0 = *(const float4*)&rb[wid * 256 + c8];
        float4 u1 = *(const float4*)&rb[wid * 256 + c8 + 4];
        float4 h0 = *(const float4*)&h[row * 256 + c8];
        float4 h1 = *(const float4*)&h[row * 256 + c8 + 4];
        float v[8];
        v[0] = h0.x + u0.x; v[1] = h0.y + u0.y; v[2] = h0.z + u0.z; v[3] = h0.w + u0.w;
        v[4] = h1.x + u1.x; v[5] = h1.y + u1.y; v[6] = h1.z + u1.z; v[7] = h1.w + u1.w;
        float s = 0.f;
        #pragma unroll
        for (int k = 0; k < 8; k++) s += v[k];
        for (int o = 16; o; o >>= 1) s += __shfl_xor_sync(0xffffffffu, s, o);
        float mu = s * (1.f / H);
        float q = 0.f;
        #pragma unroll
        for (int k = 0; k < 8; k++) { float d = v[k] - mu; q += d * d; }
        for (int o = 16; o; o >>= 1) q += __shfl_xor_sync(0xffffffffu, q, o);
        float inv = rsqrtf(q * (1.f / H) + 1e-5f);
        float* hw = h + row * 256;
        #pragma unroll
        for (int k = 0; k < 8; k++)
            hw[c8 + k] = (v[k] - mu) * inv * lng[c8 + k] + lnbeta[c8 + k];
    }
}

// ---------------------------------------------------------------------------
// aggpre[b,i,h] = sum_j A[i,j] * relu(a[b,i,h] + bb[b,j,h])   (b1 folded into bb)
// grid (hc=4, ic=4, b=8) = 128 CTAs, 256 threads.
__global__ __launch_bounds__(256) void agg_kernel(
    const float* __restrict__ a, const float* __restrict__ bbg,
    const float* __restrict__ A, float* __restrict__ out)
{
    __shared__ float bbs[128 * 64];
    int hc = blockIdx.x * 64, ic = blockIdx.y * 32, b = blockIdx.z;
    int t = threadIdx.x;
    const float* bp = bbg + b * R * H;
    for (int idx = t; idx < 2048; idx += 256) {
        int j = idx >> 4, c4 = (idx & 15) * 4;
        *(float4*)&bbs[j * 64 + c4] = *(const float4*)&bp[j * H + hc + c4];
    }
    __syncthreads();
    int hl = (t & 15) * 4;
    int i0 = ic + (t >> 4) * 2;
    float4 av0 = *(const float4*)&a[(b * R + i0) * H + hc + hl];
    float4 av1 = *(const float4*)&a[(b * R + i0 + 1) * H + hc + hl];
    float4 ac0 = {0, 0, 0, 0}, ac1 = {0, 0, 0, 0};
    const float* Ar = A + i0 * R;
    #pragma unroll 4
    for (int j = 0; j < R; j++) {
        float4 bv = *(const float4*)&bbs[j * 64 + hl];
        float w0 = __ldg(&Ar[j]);
        float w1 = __ldg(&Ar[R + j]);
        ac0.x += w0 * fmaxf(av0.x + bv.x, 0.f);
        ac0.y += w0 * fmaxf(av0.y + bv.y, 0.f);
        ac0.z += w0 * fmaxf(av0.z + bv.z, 0.f);
        ac0.w += w0 * fmaxf(av0.w + bv.w, 0.f);
        ac1.x += w1 * fmaxf(av1.x + bv.x, 0.f);
        ac1.y += w1 * fmaxf(av1.y + bv.y, 0.f);
        ac1.z += w1 * fmaxf(av1.z + bv.z, 0.f);
        ac1.w += w1 * fmaxf(av1.w + bv.w, 0.f);
    }
    *(float4*)&out[(b * R + i0) * H + hc + hl]     = ac0;
    *(float4*)&out[(b * R + i0 + 1) * H + hc + hl] = ac1;
}

// ---------------------------------------------------------------------------
// Multi-head attention for one (b, head, q-chunk of 16 rows).
__global__ __launch_bounds__(256) void attn_kernel(
    const float* __restrict__ q, const float* __restrict__ k,
    const float* __restrict__ v, float* __restrict__ ao)
{
    __shared__ float ks[128 * 65];
    __shared__ float qs[16 * 64];
    __shared__ float ls[16 * 128];
    int qc = blockIdx.x, head = blockIdx.y, b = blockIdx.z;
    int t = threadIdx.x;

    const float* kb = k + b * R * H + head * DH;
    for (int idx = t; idx < 128 * 64; idx += 256) {
        int j = idx >> 6, d = idx & 63;
        ks[j * 65 + d] = kb[j * H + d];
    }
    const float* qb = q + (b * R + qc * 16) * H + head * DH;
    for (int idx = t; idx < 16 * 64; idx += 256) {
        int r = idx >> 6, d = idx & 63;
        qs[r * 64 + d] = qb[r * H + d];
    }
    __syncthreads();

    {   // logits
        int j = t & 127, g = t >> 7;
        float acc[8];
        #pragma unroll
        for (int r = 0; r < 8; r++) acc[r] = 0.f;
        for (int d = 0; d < 64; d++) {
            float kv = ks[j * 65 + d];
            #pragma unroll
            for (int r = 0; r < 8; r++) acc[r] += qs[(g * 8 + r) * 64 + d] * kv;
        }
        #pragma unroll
        for (int r = 0; r < 8; r++) ls[(g * 8 + r) * 128 + j] = acc[r] * 0.125f;
    }
    __syncthreads();

    {   // row softmax
        int qr = t >> 4, jc = t & 15;
        float e[8]; float mx = -3e38f;
        #pragma unroll
        for (int jj = 0; jj < 8; jj++) {
            e[jj] = ls[qr * 128 + jc * 8 + jj];
            mx = fmaxf(mx, e[jj]);
        }
        for (int o = 8; o; o >>= 1) mx = fmaxf(mx, __shfl_xor_sync(0xffffffffu, mx, o));
        float s = 0.f;
        #pragma unroll
        for (int jj = 0; jj < 8; jj++) { e[jj] = expf(e[jj] - mx); s += e[jj]; }
        for (int o = 8; o; o >>= 1) s += __shfl_xor_sync(0xffffffffu, s, o);
        float inv = 1.f / s;
        #pragma unroll
        for (int jj = 0; jj < 8; jj++) ls[qr * 128 + jc * 8 + jj] = e[jj] * inv;
    }
    float* vs = ks;
    const float* vb = v + b * R * H + head * DH;
    for (int idx = t; idx < 128 * 64; idx += 256) {
        int j = idx >> 6, d = idx & 63;
        vs[j * 64 + d] = vb[j * H + d];
    }
    __syncthreads();

    {   // out = P @ V
        int qr = t >> 4, d4 = (t & 15) * 4;
        float4 acc = {0, 0, 0, 0};
        for (int j = 0; j < 128; j++) {
            float p = ls[qr * 128 + j];
            float4 vv = *(const float4*)&vs[j * 64 + d4];
            acc.x += p * vv.x; acc.y += p * vv.y;
            acc.z += p * vv.z; acc.w += p * vv.w;
        }
        *(float4*)&ao[(b * R + qc * 16 + qr) * H + head * DH + d4] = acc;
    }
}

// ---------------------------------------------------------------------------
// abar = mean_r ao; g = abar@Wo + bo; t = relu(g@roW1+rob1); logits; softmax.
__global__ void readout_kernel(const float* __restrict__ ao,
                               const float* __restrict__ Wo, const float* __restrict__ bo,
                               const float* __restrict__ roW1, const float* __restrict__ rob1,
                               const float* __restrict__ roW2, const float* __restrict__ rob2,
                               float* __restrict__ out) {
    __shared__ float s0[H], s1[H];
    __shared__ float red[8];
    int b = blockIdx.x, t = threadIdx.x;
    {
        float s = 0.f;
        const float* ap = ao + b * R * H + t;
        for (int r = 0; r < R; r++) s += ap[r * H];
        s0[t] = s * (1.f / R);
    }
    __syncthreads();
    float acc = bo[t];
    #pragma unroll 8
    for (int k = 0; k < H; k++) acc += s0[k] * Wo[k * H + t];
    s1[t] = acc;
    __syncthreads();
    acc = rob1[t];
    #pragma unroll 8
    for (int k = 0; k < H; k++) acc += s1[k] * roW1[k * H + t];
    __syncthreads();
    s0[t] = fmaxf(acc, 0.f);
    __syncthreads();
    float lg = -3e38f;
    if (t < R) {
        lg = rob2[t];
        #pragma unroll 8
        for (int k = 0; k < H; k++) lg += s0[k] * roW2[k * R + t];
    }
    float m = lg;
    for (int k = 16; k; k >>= 1) m = fmaxf(m, __shfl_xor_sync(0xffffffffu, m, k));
    if ((t & 31) == 0) red[t >> 5] = m;
    __syncthreads();
    if (t < 32) {
        float v = (t < 8) ? red[t] : -3e38f;
        for (int k = 4; k; k >>= 1) v = fmaxf(v, __shfl_xor_sync(0xffffffffu, v, k));
        if (t == 0) red[0] = v;
    }
    __syncthreads();
    float mx = red[0];
    __syncthreads();
    float e = (t < R) ? expf(lg - mx) : 0.f;
    float s = e;
    for (int k = 16; k; k >>= 1) s += __shfl_xor_sync(0xffffffffu, s, k);
    if ((t & 31) == 0) red[t >> 5] = s;
    __syncthreads();
    if (t < 32) {
        float v = (t < 8) ? red[t] : 0.f;
        for (int k = 4; k; k >>= 1) v += __shfl_xor_sync(0xffffffffu, v, k);
        if (t == 0) red[0] = v;
    }
    __syncthreads();
    float sum = red[0];
    if (t < R) out[b * R + t] = e / sum;
}

// ---------------------------------------------------------------------------
static inline GemmJob mkjob(const float* A, const float* W, float* C,
                            const float* bias = nullptr, const float* rowv = nullptr,
                            const float* colv = nullptr, const float* addend = nullptr,
                            int relu = 0) {
    GemmJob j;
    j.A = A; j.W = W; j.bias = bias; j.rowv = rowv; j.colv = colv;
    j.addend = addend; j.C = C; j.relu = relu;
    return j;
}

extern "C" void kernel_launch(void* const* d_in, const int* in_sizes, int n_in,
                              void* d_out, int out_size) {
    const float* x       = (const float*)d_in[0];
    const float* We      = (const float*)d_in[1];
    const float* be      = (const float*)d_in[2];
    const float* msg_W1  = (const float*)d_in[3];
    const float* msg_b1  = (const float*)d_in[4];
    const float* msg_W2  = (const float*)d_in[5];
    const float* msg_b2  = (const float*)d_in[6];
    const float* upd_W1  = (const float*)d_in[7];
    const float* upd_b1  = (const float*)d_in[8];
    const float* upd_W2  = (const float*)d_in[9];
    const float* upd_b2  = (const float*)d_in[10];
    const float* ln_g    = (const float*)d_in[11];
    const float* ln_b    = (const float*)d_in[12];
    const float* rule_adj= (const float*)d_in[13];
    const float* Wq      = (const float*)d_in[14];
    const float* bq      = (const float*)d_in[15];
    const float* Wk      = (const float*)d_in[16];
    const float* bk      = (const float*)d_in[17];
    const float* Wv      = (const float*)d_in[18];
    const float* bv      = (const float*)d_in[19];
    const float* Wo      = (const float*)d_in[20];
    const float* bo      = (const float*)d_in[21];
    const float* roW1    = (const float*)d_in[22];
    const float* rob1    = (const float*)d_in[23];
    const float* roW2    = (const float*)d_in[24];
    const float* rob2    = (const float*)d_in[25];
    float* out = (float*)d_out;

    float* base = nullptr;
    cudaGetSymbolAddress((void**)&base, g_buf);
    float* hb    = base + OFF_H;
    float* aact  = base + OFF_AACT;
    float* bbb   = base + OFF_BB;
    float* aggb  = base + OFF_AGG;
    float* hub   = base + OFF_HU;
    float* qb    = base + OFF_Q;
    float* kb    = base + OFF_K;
    float* vb    = base + OFF_V;
    float* aob   = base + OFF_AO;
    float* Ab    = base + OFF_ADJ;
    float* rsb   = base + OFF_RS;
    float* w2ub  = base + OFF_W2U;
    float* c2b   = base + OFF_C2;

    const int M = B * R;  // 1024
    dim3 g3(4, M / 32, 3);      // fused-3 GEMM: 384 CTAs

    setup_kernel<<<123, 256>>>(rule_adj, Ab, rsb, x, We, be, hb,
                               msg_b2, msg_W2, upd_W1, w2ub, c2b);

    for (int l = 0; l < L; l++) {
        const float* W1a = msg_W1 + l * 2 * HH;
        const float* W1b = W1a + HH;
        // fused: aact = h@W1a ; bb = h@W1b + b1 ; hu = h@Wu1a + b1u + rs*c2
        gemm_kernel<<<g3, 256>>>(
            mkjob(hb, W1a, aact),
            mkjob(hb, W1b, bbb, msg_b1 + l * H),
            mkjob(hb, upd_W1 + l * 2 * HH, hub, upd_b1 + l * H, rsb, c2b + l * H));
        agg_kernel<<<dim3(4, 4, B), 256>>>(aact, bbb, Ab, aggb);
        // fused tail: upre = relu(agg@W2u + hu); u = upre@Wu2 + b2u; h = LN(h+u)
        tail_kernel<<<M / 8, 256>>>(aggb, hub, w2ub + l * HH, upd_W2 + l * HH,
                                    upd_b2 + l * H, ln_g + l * H, ln_b + l * H, hb);
    }

    // fused q/k/v
    gemm_kernel<<<g3, 256>>>(
        mkjob(hb, Wq, qb, bq),
        mkjob(hb, Wk, kb, bk),
        mkjob(hb, Wv, vb, bv));
    attn_kernel<<<dim3(R / 16, NH, B), 256>>>(qb, kb, vb, aob);
    readout_kernel<<<B, H>>>(aob, Wo, bo, roW1, rob1, roW2, rob2, out);
    (void)in_sizes; (void)n_in; (void)out_size;
}